// round 16
// baseline (speedup 1.0000x reference)
#include <cuda_runtime.h>
#include <cuda_bf16.h>
#include <cstdint>

#define Bb   16
#define Ll   1024
#define DM   384
#define DI   768
#define NS   16
#define DTR  24
#define DBCW 56            // DTR + 2*NS
#define BLr  16384         // Bb*Ll
#define NCH  8             // scan chunks
#define CHT  128           // steps per chunk
#define NCHC 16            // conv chunks
#define CHTC 64            // conv steps per chunk

// ---------------- scratch (device globals; no allocations) ----------------
__device__ __nv_bfloat16 g_xnb[(size_t)BLr * DM];
__device__ uint32_t g_win_p[(size_t)(DM / 2) * 1536];
__device__ uint32_t g_wout_p[(size_t)(DI / 2) * DM];
__device__ uint32_t g_wx_p[2][(size_t)(DI / 2) * 64];
__device__ __nv_bfloat16 g_xh[(size_t)BLr * DI];
__device__ float         g_z[(size_t)BLr * DI];
__device__ __nv_bfloat16 g_xc[2][(size_t)BLr * DI];
__device__ float         g_dbc[2][(size_t)BLr * DBCW];
__device__ __nv_bfloat16 g_delta[2][(size_t)BLr * DI];
__device__ __nv_bfloat16 g_y[2][(size_t)BLr * DI];
__device__ float g_hc[2][Bb][NCH][NS][DI];
__device__ float g_dts[2][Bb][NCH][DI];

// ---------------- bf16 helpers ----------------
__device__ __forceinline__ uint32_t pack_bf2(float lo, float hi) {
    uint32_t r; asm("cvt.rn.bf16x2.f32 %0, %1, %2;" : "=r"(r) : "f"(hi), "f"(lo)); return r;
}
__device__ __forceinline__ float2 unpk_bf2(uint32_t v) {
    __nv_bfloat162 b = *(__nv_bfloat162*)&v; return __bfloat1622float2(b);
}
__device__ __forceinline__ uint32_t hadd2_bf2(uint32_t a, uint32_t b) {
    __nv_bfloat162 r = __hadd2(*(__nv_bfloat162*)&a, *(__nv_bfloat162*)&b);
    return *(uint32_t*)&r;
}
__device__ __forceinline__ void mma_bf16(float (&d)[4], const uint32_t (&a)[4], const uint32_t (&b)[2]) {
    asm volatile("mma.sync.aligned.m16n8k16.row.col.f32.bf16.bf16.f32 "
                 "{%0,%1,%2,%3}, {%4,%5,%6,%7}, {%8,%9}, {%0,%1,%2,%3};"
                 : "+f"(d[0]), "+f"(d[1]), "+f"(d[2]), "+f"(d[3])
                 : "r"(a[0]), "r"(a[1]), "r"(a[2]), "r"(a[3]), "r"(b[0]), "r"(b[1]));
}
__device__ __forceinline__ void cpa16(uint32_t saddr, const void* gptr) {
    asm volatile("cp.async.cg.shared.global [%0], [%1], 16;" :: "r"(saddr), "l"(gptr) : "memory");
}
#define CPA_COMMIT() asm volatile("cp.async.commit_group;" ::: "memory")
#define CPA_WAIT(n)  asm volatile("cp.async.wait_group %0;" :: "n"(n) : "memory")

// ---------------- packed f32x2 helpers ----------------
typedef unsigned long long u64t;
__device__ __forceinline__ u64t pk2(float lo, float hi) {
    u64t r; asm("mov.b64 %0, {%1, %2};" : "=l"(r) : "f"(lo), "f"(hi)); return r;
}
__device__ __forceinline__ void upk2(u64t v, float& lo, float& hi) {
    asm("mov.b64 {%0, %1}, %2;" : "=f"(lo), "=f"(hi) : "l"(v));
}
__device__ __forceinline__ u64t mul2(u64t a, u64t b) {
    u64t r; asm("mul.rn.f32x2 %0, %1, %2;" : "=l"(r) : "l"(a), "l"(b)); return r;
}
__device__ __forceinline__ u64t add2(u64t a, u64t b) {
    u64t r; asm("add.rn.f32x2 %0, %1, %2;" : "=l"(r) : "l"(a), "l"(b)); return r;
}
__device__ __forceinline__ u64t fma2(u64t a, u64t b, u64t c) {
    u64t r; asm("fma.rn.f32x2 %0, %1, %2, %3;" : "=l"(r) : "l"(a), "l"(b), "l"(c)); return r;
}

// ---------------- LayerNorm: warp per row ----------------
__global__ __launch_bounds__(256) void ln_kernel(const float* __restrict__ x,
                                                 const float* __restrict__ w,
                                                 const float* __restrict__ b) {
    int warp = threadIdx.x >> 5, lane = threadIdx.x & 31;
    int r = blockIdx.x * 8 + warp;
    const float2* xr = (const float2*)(x + (size_t)r * DM);
    float2 v[6];
    float s = 0.f, s2 = 0.f;
#pragma unroll
    for (int i = 0; i < 6; i++) {
        v[i] = xr[i * 32 + lane];
        s += v[i].x + v[i].y;
        s2 += v[i].x * v[i].x + v[i].y * v[i].y;
    }
#pragma unroll
    for (int o = 16; o; o >>= 1) {
        s  += __shfl_xor_sync(0xffffffffu, s, o);
        s2 += __shfl_xor_sync(0xffffffffu, s2, o);
    }
    float mu = s / DM;
    float rstd = rsqrtf(s2 / DM - mu * mu + 1e-5f);
    uint32_t* o = (uint32_t*)g_xnb + (size_t)r * (DM / 2);
#pragma unroll
    for (int i = 0; i < 6; i++) {
        int idx = i * 32 + lane;
        float2 wv = *(const float2*)(w + 2 * idx);
        float2 bv = *(const float2*)(b + 2 * idx);
        o[idx] = pack_bf2((v[i].x - mu) * rstd * wv.x + bv.x,
                          (v[i].y - mu) * rstd * wv.y + bv.y);
    }
}

// ---------------- fused weight transposes + bf16 packing ----------------
#define TIN  (192 * 1536)
#define TOUT (384 * 384)
#define TX   (384 * 64)
__global__ void transpose_all(const float* __restrict__ Win, const float* __restrict__ Wout,
                              const float* __restrict__ Wxf, const float* __restrict__ Wxb) {
    int i = blockIdx.x * 256 + threadIdx.x;
    if (i < TIN) {
        int k2 = i / 1536, n = i % 1536;
        float2 v = *(const float2*)(Win + (size_t)n * 384 + 2 * k2);
        g_win_p[i] = pack_bf2(v.x, v.y);
    } else if (i < TIN + TOUT) {
        int j = i - TIN;
        int k2 = j / 384, n = j % 384;
        float2 v = *(const float2*)(Wout + (size_t)n * 768 + 2 * k2);
        g_wout_p[j] = pack_bf2(v.x, v.y);
    } else if (i < TIN + TOUT + TX) {
        int j = i - TIN - TOUT;
        int k2 = j / 64, n = j % 64;
        if (n < 56) {
            float2 vf = *(const float2*)(Wxf + (size_t)n * 768 + 2 * k2);
            float2 vb = *(const float2*)(Wxb + (size_t)n * 768 + 2 * k2);
            g_wx_p[0][j] = pack_bf2(vf.x, vf.y);
            g_wx_p[1][j] = pack_bf2(vb.x, vb.y);
        } else {
            g_wx_p[0][j] = 0u; g_wx_p[1][j] = 0u;
        }
    }
}

// ---------------- mm_in: [xh|z] = xn @ Win  (M=16384,N=1536,K=384), cp.async dbuf ----------------
__global__ __launch_bounds__(256, 2) void mm_in_bf16() {
    const int K = 384, N = 1536, T = 12;
    __shared__ uint32_t As[2][128][20];
    __shared__ uint32_t Bs[2][16][136];
    int tid = threadIdx.x, lane = tid & 31, wid = tid >> 5;
    int wr = (wid & 3) * 32, wc = (wid >> 2) * 64;
    int g = lane >> 2, tg = lane & 3;
    const uint32_t* Ap = (const uint32_t*)g_xnb + (size_t)blockIdx.y * 128 * (K / 2);
    const uint32_t* Bp = g_win_p + blockIdx.x * 128;
    float acc[2][8][4] = {};

    int ar0 = tid >> 2, ar1 = (tid + 256) >> 2, ac = (tid & 3) * 4;
    int bk0 = tid >> 5, bk1 = (tid + 256) >> 5, bn = (tid & 31) * 4;
    uint32_t sA0[2], sA1[2], sB0[2], sB1[2];
#pragma unroll
    for (int s = 0; s < 2; s++) {
        sA0[s] = (uint32_t)__cvta_generic_to_shared(&As[s][ar0][ac]);
        sA1[s] = (uint32_t)__cvta_generic_to_shared(&As[s][ar1][ac]);
        sB0[s] = (uint32_t)__cvta_generic_to_shared(&Bs[s][bk0][bn]);
        sB1[s] = (uint32_t)__cvta_generic_to_shared(&Bs[s][bk1][bn]);
    }
    cpa16(sA0[0], Ap + (size_t)ar0 * (K / 2) + ac);
    cpa16(sA1[0], Ap + (size_t)ar1 * (K / 2) + ac);
    cpa16(sB0[0], Bp + (size_t)bk0 * N + bn);
    cpa16(sB1[0], Bp + (size_t)bk1 * N + bn);
    CPA_COMMIT();

    for (int i = 0; i < T; i++) {
        int s = i & 1;
        if (i + 1 < T) {
            int kh = (i + 1) * 16;
            cpa16(sA0[s ^ 1], Ap + (size_t)ar0 * (K / 2) + kh + ac);
            cpa16(sA1[s ^ 1], Ap + (size_t)ar1 * (K / 2) + kh + ac);
            cpa16(sB0[s ^ 1], Bp + (size_t)(kh + bk0) * N + bn);
            cpa16(sB1[s ^ 1], Bp + (size_t)(kh + bk1) * N + bn);
            CPA_COMMIT();
            CPA_WAIT(1);
        } else {
            CPA_WAIT(0);
        }
        __syncthreads();
#pragma unroll
        for (int ks = 0; ks < 2; ks++) {
            int kb2 = ks * 8;
            uint32_t af[2][4], bf[8][2];
#pragma unroll
            for (int mi = 0; mi < 2; mi++) {
                int r0 = wr + mi * 16;
                af[mi][0] = As[s][r0 + g][kb2 + tg];
                af[mi][1] = As[s][r0 + g + 8][kb2 + tg];
                af[mi][2] = As[s][r0 + g][kb2 + tg + 4];
                af[mi][3] = As[s][r0 + g + 8][kb2 + tg + 4];
            }
#pragma unroll
            for (int ni = 0; ni < 8; ni++) {
                bf[ni][0] = Bs[s][kb2 + tg][wc + ni * 8 + g];
                bf[ni][1] = Bs[s][kb2 + tg + 4][wc + ni * 8 + g];
            }
#pragma unroll
            for (int mi = 0; mi < 2; mi++)
#pragma unroll
                for (int ni = 0; ni < 8; ni++) mma_bf16(acc[mi][ni], af[mi], bf[ni]);
        }
        __syncthreads();
    }
    size_t rbase = (size_t)blockIdx.y * 128;
    if (blockIdx.x < 6) {
        uint32_t* C = (uint32_t*)g_xh;
        int cb = blockIdx.x * 128;
#pragma unroll
        for (int mi = 0; mi < 2; mi++)
#pragma unroll
            for (int ni = 0; ni < 8; ni++) {
                int r = wr + mi * 16 + g, c = cb + wc + ni * 8 + tg * 2;
                C[((rbase + r) * DI + c) >> 1]     = pack_bf2(acc[mi][ni][0], acc[mi][ni][1]);
                C[((rbase + r + 8) * DI + c) >> 1] = pack_bf2(acc[mi][ni][2], acc[mi][ni][3]);
            }
    } else {
        int cb = (blockIdx.x - 6) * 128;
#pragma unroll
        for (int mi = 0; mi < 2; mi++)
#pragma unroll
            for (int ni = 0; ni < 8; ni++) {
                int r = wr + mi * 16 + g, c = cb + wc + ni * 8 + tg * 2;
                *(float2*)(g_z + (rbase + r) * DI + c)     = make_float2(acc[mi][ni][0], acc[mi][ni][1]);
                *(float2*)(g_z + (rbase + r + 8) * DI + c) = make_float2(acc[mi][ni][2], acc[mi][ni][3]);
            }
    }
}

// ---------------- mm_out: out = x + (yf+yr) @ Wout (M=16384,N=384,K=768), dbuf 1-sync ----------------
__global__ __launch_bounds__(256, 2) void mm_out_bf16(const float* __restrict__ xres,
                                                      float* __restrict__ out) {
    const int K = 768, N = 384, T = 24;
    __shared__ uint32_t As[2][128][20];
    __shared__ uint32_t Bs[2][16][136];
    int tid = threadIdx.x, lane = tid & 31, wid = tid >> 5;
    int wr = (wid & 3) * 32, wc = (wid >> 2) * 64;
    int g = lane >> 2, tg = lane & 3;
    const uint32_t* A0 = (const uint32_t*)g_y[0] + (size_t)blockIdx.y * 128 * (K / 2);
    const uint32_t* A1 = (const uint32_t*)g_y[1] + (size_t)blockIdx.y * 128 * (K / 2);
    const uint32_t* Bp = g_wout_p + blockIdx.x * 128;
    float acc[2][8][4] = {};

    int ar0 = tid >> 2, ar1 = (tid + 256) >> 2, ac = (tid & 3) * 4;
    int bk0 = tid >> 5, bk1 = (tid + 256) >> 5, bn = (tid & 31) * 4;
    uint4 ra0, ra1, sa0, sa1, rb0, rb1;
    ra0 = *(const uint4*)(A0 + (size_t)ar0 * (K / 2) + ac);
    sa0 = *(const uint4*)(A1 + (size_t)ar0 * (K / 2) + ac);
    ra1 = *(const uint4*)(A0 + (size_t)ar1 * (K / 2) + ac);
    sa1 = *(const uint4*)(A1 + (size_t)ar1 * (K / 2) + ac);
    rb0 = *(const uint4*)(Bp + (size_t)bk0 * N + bn);
    rb1 = *(const uint4*)(Bp + (size_t)bk1 * N + bn);

    for (int i = 0; i < T; i++) {
        int s = i & 1;
        As[s][ar0][ac + 0] = hadd2_bf2(ra0.x, sa0.x);
        As[s][ar0][ac + 1] = hadd2_bf2(ra0.y, sa0.y);
        As[s][ar0][ac + 2] = hadd2_bf2(ra0.z, sa0.z);
        As[s][ar0][ac + 3] = hadd2_bf2(ra0.w, sa0.w);
        As[s][ar1][ac + 0] = hadd2_bf2(ra1.x, sa1.x);
        As[s][ar1][ac + 1] = hadd2_bf2(ra1.y, sa1.y);
        As[s][ar1][ac + 2] = hadd2_bf2(ra1.z, sa1.z);
        As[s][ar1][ac + 3] = hadd2_bf2(ra1.w, sa1.w);
        *(uint4*)&Bs[s][bk0][bn] = rb0;
        *(uint4*)&Bs[s][bk1][bn] = rb1;
        __syncthreads();
        if (i + 1 < T) {
            int kh = (i + 1) * 16;
            ra0 = *(const uint4*)(A0 + (size_t)ar0 * (K / 2) + kh + ac);
            sa0 = *(const uint4*)(A1 + (size_t)ar0 * (K / 2) + kh + ac);
            ra1 = *(const uint4*)(A0 + (size_t)ar1 * (K / 2) + kh + ac);
            sa1 = *(const uint4*)(A1 + (size_t)ar1 * (K / 2) + kh + ac);
            rb0 = *(const uint4*)(Bp + (size_t)(kh + bk0) * N + bn);
            rb1 = *(const uint4*)(Bp + (size_t)(kh + bk1) * N + bn);
        }
#pragma unroll
        for (int ks = 0; ks < 2; ks++) {
            int kb2 = ks * 8;
            uint32_t af[2][4], bf[8][2];
#pragma unroll
            for (int mi = 0; mi < 2; mi++) {
                int r0 = wr + mi * 16;
                af[mi][0] = As[s][r0 + g][kb2 + tg];
                af[mi][1] = As[s][r0 + g + 8][kb2 + tg];
                af[mi][2] = As[s][r0 + g][kb2 + tg + 4];
                af[mi][3] = As[s][r0 + g + 8][kb2 + tg + 4];
            }
#pragma unroll
            for (int ni = 0; ni < 8; ni++) {
                bf[ni][0] = Bs[s][kb2 + tg][wc + ni * 8 + g];
                bf[ni][1] = Bs[s][kb2 + tg + 4][wc + ni * 8 + g];
            }
#pragma unroll
            for (int mi = 0; mi < 2; mi++)
#pragma unroll
                for (int ni = 0; ni < 8; ni++) mma_bf16(acc[mi][ni], af[mi], bf[ni]);
        }
        __syncthreads();
    }
    size_t rbase = (size_t)blockIdx.y * 128;
    int cbase = blockIdx.x * 128;
#pragma unroll
    for (int mi = 0; mi < 2; mi++)
#pragma unroll
        for (int ni = 0; ni < 8; ni++) {
            int r = wr + mi * 16 + g, c = wc + ni * 8 + tg * 2;
            size_t o0 = (rbase + r) * N + cbase + c;
            size_t o1 = (rbase + r + 8) * N + cbase + c;
            out[o0]     = acc[mi][ni][0] + xres[o0];
            out[o0 + 1] = acc[mi][ni][1] + xres[o0 + 1];
            out[o1]     = acc[mi][ni][2] + xres[o1];
            out[o1 + 1] = acc[mi][ni][3] + xres[o1 + 1];
        }
}

// ---------------- mm_x: dbc = xc @ Wx (M=16384,N=64->56,K=768), cp.async dbuf ----------------
__global__ __launch_bounds__(256, 2) void mm_x_bf16() {
    const int K = 768, T = 24;
    int dir = blockIdx.z;
    __shared__ uint32_t As[2][128][20];
    __shared__ uint32_t Bs[2][16][72];
    int tid = threadIdx.x, lane = tid & 31, wid = tid >> 5;
    int wr = wid * 16;
    int g = lane >> 2, tg = lane & 3;
    const uint32_t* Ap = (const uint32_t*)g_xc[dir] + (size_t)blockIdx.y * 128 * (K / 2);
    const uint32_t* Bp = g_wx_p[dir];
    float acc[8][4] = {};

    int ar0 = tid >> 2, ar1 = (tid + 256) >> 2, ac = (tid & 3) * 4;
    int bk = tid >> 4, bn = (tid & 15) * 4;
    uint32_t sA0[2], sA1[2], sB[2];
#pragma unroll
    for (int s = 0; s < 2; s++) {
        sA0[s] = (uint32_t)__cvta_generic_to_shared(&As[s][ar0][ac]);
        sA1[s] = (uint32_t)__cvta_generic_to_shared(&As[s][ar1][ac]);
        sB[s]  = (uint32_t)__cvta_generic_to_shared(&Bs[s][bk][bn]);
    }
    cpa16(sA0[0], Ap + (size_t)ar0 * (K / 2) + ac);
    cpa16(sA1[0], Ap + (size_t)ar1 * (K / 2) + ac);
    cpa16(sB[0],  Bp + (size_t)bk * 64 + bn);
    CPA_COMMIT();

    for (int i = 0; i < T; i++) {
        int s = i & 1;
        if (i + 1 < T) {
            int kh = (i + 1) * 16;
            cpa16(sA0[s ^ 1], Ap + (size_t)ar0 * (K / 2) + kh + ac);
            cpa16(sA1[s ^ 1], Ap + (size_t)ar1 * (K / 2) + kh + ac);
            cpa16(sB[s ^ 1],  Bp + (size_t)(kh + bk) * 64 + bn);
            CPA_COMMIT();
            CPA_WAIT(1);
        } else {
            CPA_WAIT(0);
        }
        __syncthreads();
#pragma unroll
        for (int ks = 0; ks < 2; ks++) {
            int kb2 = ks * 8;
            uint32_t af[4], bf[8][2];
            af[0] = As[s][wr + g][kb2 + tg];
            af[1] = As[s][wr + g + 8][kb2 + tg];
            af[2] = As[s][wr + g][kb2 + tg + 4];
            af[3] = As[s][wr + g + 8][kb2 + tg + 4];
#pragma unroll
            for (int ni = 0; ni < 8; ni++) {
                bf[ni][0] = Bs[s][kb2 + tg][ni * 8 + g];
                bf[ni][1] = Bs[s][kb2 + tg + 4][ni * 8 + g];
            }
#pragma unroll
            for (int ni = 0; ni < 8; ni++) mma_bf16(acc[ni], af, bf[ni]);
        }
        __syncthreads();
    }
    size_t rbase = (size_t)blockIdx.y * 128;
#pragma unroll
    for (int ni = 0; ni < 8; ni++) {
        int c = ni * 8 + tg * 2;
        if (c < 56) {
            int r = wr + g;
            float* o0 = g_dbc[dir] + (rbase + r) * DBCW + c;
            float* o1 = g_dbc[dir] + (rbase + r + 8) * DBCW + c;
            o0[0] = acc[ni][0]; o0[1] = acc[ni][1];
            o1[0] = acc[ni][2]; o1[1] = acc[ni][3];
        }
    }
}

// ---------------- causal conv: 16 chunks, 2-block channel split, packed ----------------
__global__ __launch_bounds__(192) void conv_chunk_kernel(const float* __restrict__ cw_f,
                                                         const float* __restrict__ cb_f,
                                                         const float* __restrict__ cw_b,
                                                         const float* __restrict__ cb_b) {
    int dir = blockIdx.z;
    int bb = blockIdx.y >> 4, ch = blockIdx.y & 15;
    int d2 = blockIdx.x * 192 + threadIdx.x;
    int d = d2 * 2;
    int l0 = ch * CHTC;
    const float* cw = dir ? cw_b : cw_f;
    float4 wa = *(const float4*)(cw + d * 4);
    float4 wb = *(const float4*)(cw + d * 4 + 4);
    float2 bias = *(const float2*)((dir ? cb_b : cb_f) + d);
    const uint32_t* xp = (const uint32_t*)g_xh + (size_t)bb * Ll * (DI / 2) + d2;
    uint32_t* yo = (uint32_t*)g_xc[dir] + ((size_t)bb * Ll + l0) * (DI / 2) + d2;
    float a1 = 0.f, a2 = 0.f, a3 = 0.f;
    float b1 = 0.f, b2 = 0.f, b3 = 0.f;
    {
        int lk;
        lk = l0 - 1; if (lk >= 0) { float2 v = unpk_bf2(xp[(size_t)(dir ? (Ll - 1 - lk) : lk) * (DI / 2)]); a1 = v.x; b1 = v.y; }
        lk = l0 - 2; if (lk >= 0) { float2 v = unpk_bf2(xp[(size_t)(dir ? (Ll - 1 - lk) : lk) * (DI / 2)]); a2 = v.x; b2 = v.y; }
        lk = l0 - 3; if (lk >= 0) { float2 v = unpk_bf2(xp[(size_t)(dir ? (Ll - 1 - lk) : lk) * (DI / 2)]); a3 = v.x; b3 = v.y; }
    }
    const uint32_t* xq = xp + (size_t)(dir ? (Ll - 1 - l0) : l0) * (DI / 2);
    intptr_t step = (dir ? -(intptr_t)(DI / 2) : (intptr_t)(DI / 2));
    for (int l = 0; l < CHTC; l += 4) {
        float2 xv[4];
#pragma unroll
        for (int j = 0; j < 4; j++) { xv[j] = unpk_bf2(*xq); xq += step; }
#pragma unroll
        for (int j = 0; j < 4; j++) {
            float sa = bias.x + wa.w * xv[j].x + wa.z * a1 + wa.y * a2 + wa.x * a3;
            float sb = bias.y + wb.w * xv[j].y + wb.z * b1 + wb.y * b2 + wb.x * b3;
            a3 = a2; a2 = a1; a1 = xv[j].x;
            b3 = b2; b2 = b1; b1 = xv[j].y;
            sa = sa * (1.f / (1.f + __expf(-sa)));
            sb = sb * (1.f / (1.f + __expf(-sb)));
            yo[(size_t)(l + j) * (DI / 2)] = pack_bf2(sa, sb);
        }
    }
}

// ---------------- dt_proj + softplus (float4 smem, fast log) ----------------
__global__ __launch_bounds__(256) void dtproj_kernel(const float* __restrict__ dtw_f,
                                                     const float* __restrict__ dtb_f,
                                                     const float* __restrict__ dtw_b,
                                                     const float* __restrict__ dtb_b) {
    int dir = blockIdx.z;
    int col = blockIdx.x * 256 + threadIdx.x;
    int r0 = blockIdx.y * 32;
    const float* Wd = dir ? dtw_b : dtw_f;
    float4 w[6];
#pragma unroll
    for (int j = 0; j < 6; j++) w[j] = *(const float4*)(Wd + col * DTR + j * 4);
    float bias = (dir ? dtb_b : dtb_f)[col];
    __shared__ __align__(16) float sdt[32 * DTR];
    if (threadIdx.x < 192) {
        int rr = threadIdx.x / 6, j = threadIdx.x % 6;
        *(float4*)&sdt[rr * DTR + j * 4] =
            *(const float4*)(g_dbc[dir] + (size_t)(r0 + rr) * DBCW + j * 4);
    }
    __syncthreads();
    for (int rr = 0; rr < 32; rr++) {
        float acc = bias;
#pragma unroll
        for (int j = 0; j < 6; j++) {
            float4 v = *(const float4*)&sdt[rr * DTR + j * 4];
            acc += v.x * w[j].x + v.y * w[j].y + v.z * w[j].z + v.w * w[j].w;
        }
        float sp = (acc > 20.f) ? acc : __logf(1.f + __expf(acc));
        g_delta[dir][(size_t)(r0 + rr) * DI + col] = __float2bfloat16(sp);
    }
}

// ---------------- packed power tree: pw[n] = q^(n+1) (f32x2) ----------------
__device__ __forceinline__ void pow_tree2(u64t q, u64t (&pw)[NS]) {
    u64t q2 = mul2(q, q), q4 = mul2(q2, q2), q8 = mul2(q4, q4);
    u64t q3 = mul2(q2, q), q5 = mul2(q4, q), q6 = mul2(q4, q2), q7 = mul2(q4, q3);
    pw[0] = q;  pw[1] = q2; pw[2] = q3; pw[3] = q4;
    pw[4] = q5; pw[5] = q6; pw[6] = q7; pw[7] = q8;
    pw[8]  = mul2(q8, q);  pw[9]  = mul2(q8, q2); pw[10] = mul2(q8, q3); pw[11] = mul2(q8, q4);
    pw[12] = mul2(q8, q5); pw[13] = mul2(q8, q6); pw[14] = mul2(q8, q7); pw[15] = mul2(q8, q8);
}

// ---------------- scan pass 1: packed 2-ch, per-chunk local states + sum(dt) ----------------
__global__ __launch_bounds__(64) void scan_pass1(const float* __restrict__ Alog_f,
                                                 const float* __restrict__ Alog_b) {
    int dir = blockIdx.z;
    int bb = blockIdx.y >> 3, ch = blockIdx.y & 7;
    int d2 = blockIdx.x * 64 + threadIdx.x;    // channel pair
    int d = d2 * 2;
    int tb = ch * CHT;
    const float* Alog = dir ? Alog_b : Alog_f;
    const uint32_t* delta = (const uint32_t*)g_delta[dir] + ((size_t)bb * Ll + tb) * (DI / 2) + d2;
    const uint32_t* u     = (const uint32_t*)g_xc[dir]   + ((size_t)bb * Ll + tb) * (DI / 2) + d2;
    const float* dbc      = g_dbc[dir] + ((size_t)bb * Ll + tb) * DBCW;

    float Aa[NS], Ab[NS];
#pragma unroll
    for (int n = 0; n < NS; n++) {
        Aa[n] = -__expf(Alog[d * NS + n]);
        Ab[n] = -__expf(Alog[(d + 1) * NS + n]);
    }
    bool fast = true;
#pragma unroll
    for (int n = 1; n < NS; n++) {
        fast = fast && (fabsf(Aa[n] - (float)(n + 1) * Aa[0]) <= 1e-5f * fabsf(Aa[n]));
        fast = fast && (fabsf(Ab[n] - (float)(n + 1) * Ab[0]) <= 1e-5f * fabsf(Ab[n]));
    }

    __shared__ u64t sB2[8][NS];
    u64t h2[NS];
#pragma unroll
    for (int n = 0; n < NS; n++) h2[n] = 0ull;
    u64t sdt2 = 0ull;

    for (int t0 = 0; t0 < CHT; t0 += 8) {
        uint32_t draw[8], uraw[8];
#pragma unroll
        for (int i = 0; i < 8; i++) {
            draw[i] = delta[(size_t)(t0 + i) * (DI / 2)];
            uraw[i] = u[(size_t)(t0 + i) * (DI / 2)];
        }
        __syncthreads();
        {
            int i0 = (int)threadIdx.x;
            int tt = i0 >> 4, n = i0 & 15;
            float v0 = dbc[(size_t)(t0 + tt) * DBCW + DTR + n];
            sB2[tt][n] = pk2(v0, v0);
            int i1 = i0 + 64;
            tt = i1 >> 4; n = i1 & 15;
            float v1 = dbc[(size_t)(t0 + tt) * DBCW + DTR + n];
            sB2[tt][n] = pk2(v1, v1);
        }
        __syncthreads();
#pragma unroll
        for (int i = 0; i < 8; i++) {
            float2 df = unpk_bf2(draw[i]);
            float2 uf = unpk_bf2(uraw[i]);
            u64t dt2 = pk2(df.x, df.y);
            u64t du2 = mul2(dt2, pk2(uf.x, uf.y));
            sdt2 = add2(sdt2, dt2);
            u64t pw[NS];
            if (fast) {
                pow_tree2(pk2(__expf(df.x * Aa[0]), __expf(df.y * Ab[0])), pw);
            } else {
#pragma unroll
                for (int n = 0; n < NS; n++)
                    pw[n] = pk2(__expf(df.x * Aa[n]), __expf(df.y * Ab[n]));
            }
#pragma unroll
            for (int n = 0; n < NS; n++)
                h2[n] = fma2(du2, sB2[i][n], mul2(h2[n], pw[n]));
        }
    }
#pragma unroll
    for (int n = 0; n < NS; n++) {
        float lo, hi; upk2(h2[n], lo, hi);
        *(float2*)&g_hc[dir][bb][ch][n][d] = make_float2(lo, hi);
    }
    {
        float lo, hi; upk2(sdt2, lo, hi);
        *(float2*)&g_dts[dir][bb][ch][d] = make_float2(lo, hi);
    }
}

// ---------------- scan pass 3: packed 2-ch, entry combine + full scan ----------------
__global__ __launch_bounds__(64) void scan_pass3(const float* __restrict__ Alog_f,
                                                 const float* __restrict__ Alog_b,
                                                 const float* __restrict__ Dv_f,
                                                 const float* __restrict__ Dv_b) {
    int dir = blockIdx.z;
    int bb = blockIdx.y >> 3, ch = blockIdx.y & 7;
    int d2 = blockIdx.x * 64 + threadIdx.x;
    int d = d2 * 2;
    int tb = ch * CHT;
    const float* Alog = dir ? Alog_b : Alog_f;
    const float* Dvp  = dir ? Dv_b  : Dv_f;
    const uint32_t* delta = (const uint32_t*)g_delta[dir] + ((size_t)bb * Ll + tb) * (DI / 2) + d2;
    const uint32_t* u     = (const uint32_t*)g_xc[dir]   + ((size_t)bb * Ll + tb) * (DI / 2) + d2;
    const float* dbc      = g_dbc[dir] + ((size_t)bb * Ll + tb) * DBCW;
    const float* zb       = g_z + (size_t)bb * Ll * DI + d;
    uint32_t* yout        = (uint32_t*)g_y[dir] + (size_t)bb * Ll * (DI / 2) + d2;

    float Aa[NS], Ab[NS];
#pragma unroll
    for (int n = 0; n < NS; n++) {
        Aa[n] = -__expf(Alog[d * NS + n]);
        Ab[n] = -__expf(Alog[(d + 1) * NS + n]);
    }
    bool fast = true;
#pragma unroll
    for (int n = 1; n < NS; n++) {
        fast = fast && (fabsf(Aa[n] - (float)(n + 1) * Aa[0]) <= 1e-5f * fabsf(Aa[n]));
        fast = fast && (fabsf(Ab[n] - (float)(n + 1) * Ab[0]) <= 1e-5f * fabsf(Ab[n]));
    }
    float2 Dvv = *(const float2*)(Dvp + d);
    u64t Dv2 = pk2(Dvv.x, Dvv.y);

    // entry state: combine chunks 0..ch-1
    u64t h2[NS];
#pragma unroll
    for (int n = 0; n < NS; n++) h2[n] = 0ull;
    for (int j = 0; j < ch; j++) {
        float2 S = *(const float2*)&g_dts[dir][bb][j][d];
        u64t pw[NS];
        if (fast) {
            pow_tree2(pk2(__expf(Aa[0] * S.x), __expf(Ab[0] * S.y)), pw);
        } else {
#pragma unroll
            for (int n = 0; n < NS; n++)
                pw[n] = pk2(__expf(Aa[n] * S.x), __expf(Ab[n] * S.y));
        }
#pragma unroll
        for (int n = 0; n < NS; n++) {
            float2 hc = *(const float2*)&g_hc[dir][bb][j][n][d];
            h2[n] = fma2(pw[n], h2[n], pk2(hc.x, hc.y));
        }
    }

    __shared__ u64t sBC2[8][32];   // [t][0..15]=B dup, [16..31]=C dup
    for (int t0 = 0; t0 < CHT; t0 += 8) {
        uint32_t draw[8], uraw[8];
        float2 zl[8];
#pragma unroll
        for (int i = 0; i < 8; i++) {
            draw[i] = delta[(size_t)(t0 + i) * (DI / 2)];
            uraw[i] = u[(size_t)(t0 + i) * (DI / 2)];
            int t = tb + t0 + i;
            int op = dir ? (Ll - 1 - t) : t;
            zl[i] = *(const float2*)(zb + (size_t)op * DI);
        }
        __syncthreads();
#pragma unroll
        for (int j = 0; j < 4; j++) {
            int i = (int)threadIdx.x + 64 * j;
            int tt = i >> 5, k = i & 31;
            float v = dbc[(size_t)(t0 + tt) * DBCW + DTR + k];
            sBC2[tt][k] = pk2(v, v);
        }
        __syncthreads();
#pragma unroll
        for (int i = 0; i < 8; i++) {
            float2 df = unpk_bf2(draw[i]);
            float2 uf = unpk_bf2(uraw[i]);
            u64t dt2 = pk2(df.x, df.y);
            u64t u2  = pk2(uf.x, uf.y);
            u64t du2 = mul2(dt2, u2);
            u64t pw[NS];
            if (fast) {
                pow_tree2(pk2(__expf(df.x * Aa[0]), __expf(df.y * Ab[0])), pw);
            } else {
#pragma unroll
                for (int n = 0; n < NS; n++)
                    pw[n] = pk2(__expf(df.x * Aa[n]), __expf(df.y * Ab[n]));
            }
            u64t y2 = 0ull;
#pragma unroll
            for (int n = 0; n < NS; n++) {
                h2[n] = fma2(du2, sBC2[i][n], mul2(h2[n], pw[n]));
                y2 = fma2(h2[n], sBC2[i][16 + n], y2);
            }
            y2 = fma2(u2, Dv2, y2);
            float ya, yb; upk2(y2, ya, yb);
            float sza = zl[i].x * (1.f / (1.f + __expf(-zl[i].x)));
            float szb = zl[i].y * (1.f / (1.f + __expf(-zl[i].y)));
            int t = tb + t0 + i;
            int op = dir ? (Ll - 1 - t) : t;
            yout[(size_t)op * (DI / 2)] = pack_bf2(ya * sza, yb * szb);
        }
    }
}

// ---------------- launch ----------------
extern "C" void kernel_launch(void* const* d_in, const int* in_sizes, int n_in,
                              void* d_out, int out_size) {
    const float* x        = (const float*)d_in[0];
    const float* ln_w     = (const float*)d_in[1];
    const float* ln_b     = (const float*)d_in[2];
    const float* in_proj  = (const float*)d_in[3];
    const float* out_proj = (const float*)d_in[4];
    const float* cw_f     = (const float*)d_in[5];
    const float* cb_f     = (const float*)d_in[6];
    const float* xw_f     = (const float*)d_in[7];
    const float* dtw_f    = (const float*)d_in[8];
    const float* dtb_f    = (const float*)d_in[9];
    const float* Alog_f   = (const float*)d_in[10];
    const float* Dv_f     = (const float*)d_in[11];
    const float* cw_b     = (const float*)d_in[12];
    const float* cb_b     = (const float*)d_in[13];
    const float* xw_b     = (const float*)d_in[14];
    const float* dtw_b    = (const float*)d_in[15];
    const float* dtb_b    = (const float*)d_in[16];
    const float* Alog_b   = (const float*)d_in[17];
    const float* Dv_b     = (const float*)d_in[18];
    float* out = (float*)d_out;

    ln_kernel<<<BLr / 8, 256>>>(x, ln_w, ln_b);
    transpose_all<<<(TIN + TOUT + TX + 255) / 256, 256>>>(in_proj, out_proj, xw_f, xw_b);
    mm_in_bf16<<<dim3(12, 128), 256>>>();
    conv_chunk_kernel<<<dim3(2, Bb * NCHC, 2), 192>>>(cw_f, cb_f, cw_b, cb_b);
    mm_x_bf16<<<dim3(1, 128, 2), 256>>>();
    dtproj_kernel<<<dim3(3, BLr / 32, 2), 256>>>(dtw_f, dtb_f, dtw_b, dtb_b);
    scan_pass1<<<dim3(6, 128, 2), 64>>>(Alog_f, Alog_b);
    scan_pass3<<<dim3(6, 128, 2), 64>>>(Alog_f, Alog_b, Dv_f, Dv_b);
    mm_out_bf16<<<dim3(3, 128), 256>>>(x, out);
}

// round 17
// speedup vs baseline: 1.5590x; 1.5590x over previous
#include <cuda_runtime.h>
#include <cuda_bf16.h>
#include <cstdint>

#define Bb   16
#define Ll   1024
#define DM   384
#define DI   768
#define NS   16
#define DTR  24
#define DBCW 56            // DTR + 2*NS
#define BLr  16384         // Bb*Ll
#define NCH  8             // scan chunks
#define CHT  128           // steps per chunk
#define NCHC 16            // conv chunks
#define CHTC 64            // conv steps per chunk

// ---------------- scratch (device globals; no allocations) ----------------
__device__ __nv_bfloat16 g_xnb[(size_t)BLr * DM];
__device__ uint32_t g_win_p[(size_t)(DM / 2) * 1536];
__device__ uint32_t g_wout_p[(size_t)(DI / 2) * DM];
__device__ uint32_t g_wx_p[2][(size_t)(DI / 2) * 64];
__device__ __nv_bfloat16 g_xh[(size_t)BLr * DI];
__device__ float         g_z[(size_t)BLr * DI];
__device__ __nv_bfloat16 g_xc[2][(size_t)BLr * DI];
__device__ float         g_dbc[2][(size_t)BLr * DBCW];
__device__ __nv_bfloat16 g_delta[2][(size_t)BLr * DI];
__device__ __nv_bfloat16 g_y[2][(size_t)BLr * DI];
__device__ float g_hc[2][Bb][NCH][NS][DI];
__device__ float g_dts[2][Bb][NCH][DI];

// ---------------- bf16 helpers ----------------
__device__ __forceinline__ uint32_t pack_bf2(float lo, float hi) {
    uint32_t r; asm("cvt.rn.bf16x2.f32 %0, %1, %2;" : "=r"(r) : "f"(hi), "f"(lo)); return r;
}
__device__ __forceinline__ float2 unpk_bf2(uint32_t v) {
    __nv_bfloat162 b = *(__nv_bfloat162*)&v; return __bfloat1622float2(b);
}
__device__ __forceinline__ uint32_t hadd2_bf2(uint32_t a, uint32_t b) {
    __nv_bfloat162 r = __hadd2(*(__nv_bfloat162*)&a, *(__nv_bfloat162*)&b);
    return *(uint32_t*)&r;
}
__device__ __forceinline__ void mma_bf16(float (&d)[4], const uint32_t (&a)[4], const uint32_t (&b)[2]) {
    asm volatile("mma.sync.aligned.m16n8k16.row.col.f32.bf16.bf16.f32 "
                 "{%0,%1,%2,%3}, {%4,%5,%6,%7}, {%8,%9}, {%0,%1,%2,%3};"
                 : "+f"(d[0]), "+f"(d[1]), "+f"(d[2]), "+f"(d[3])
                 : "r"(a[0]), "r"(a[1]), "r"(a[2]), "r"(a[3]), "r"(b[0]), "r"(b[1]));
}
__device__ __forceinline__ void cpa16(uint32_t saddr, const void* gptr) {
    asm volatile("cp.async.cg.shared.global [%0], [%1], 16;" :: "r"(saddr), "l"(gptr) : "memory");
}
#define CPA_COMMIT() asm volatile("cp.async.commit_group;" ::: "memory")
#define CPA_WAIT(n)  asm volatile("cp.async.wait_group %0;" :: "n"(n) : "memory")

// ---------------- fused prep: LayerNorm (blocks 0..2047) + weight packing ----------------
#define TIN  (192 * 1536)
#define TOUT (384 * 384)
#define TX   (384 * 64)
#define LNBLK (BLr / 8)
__global__ __launch_bounds__(256) void prep_kernel(const float* __restrict__ x,
                                                   const float* __restrict__ w,
                                                   const float* __restrict__ b,
                                                   const float* __restrict__ Win,
                                                   const float* __restrict__ Wout,
                                                   const float* __restrict__ Wxf,
                                                   const float* __restrict__ Wxb) {
    if (blockIdx.x < LNBLK) {
        int warp = threadIdx.x >> 5, lane = threadIdx.x & 31;
        int r = blockIdx.x * 8 + warp;
        const float2* xr = (const float2*)(x + (size_t)r * DM);
        float2 v[6];
        float s = 0.f, s2 = 0.f;
#pragma unroll
        for (int i = 0; i < 6; i++) {
            v[i] = xr[i * 32 + lane];
            s += v[i].x + v[i].y;
            s2 += v[i].x * v[i].x + v[i].y * v[i].y;
        }
#pragma unroll
        for (int o = 16; o; o >>= 1) {
            s  += __shfl_xor_sync(0xffffffffu, s, o);
            s2 += __shfl_xor_sync(0xffffffffu, s2, o);
        }
        float mu = s / DM;
        float rstd = rsqrtf(s2 / DM - mu * mu + 1e-5f);
        uint32_t* o = (uint32_t*)g_xnb + (size_t)r * (DM / 2);
#pragma unroll
        for (int i = 0; i < 6; i++) {
            int idx = i * 32 + lane;
            float2 wv = *(const float2*)(w + 2 * idx);
            float2 bv = *(const float2*)(b + 2 * idx);
            o[idx] = pack_bf2((v[i].x - mu) * rstd * wv.x + bv.x,
                              (v[i].y - mu) * rstd * wv.y + bv.y);
        }
    } else {
        int i = (blockIdx.x - LNBLK) * 256 + threadIdx.x;
        if (i < TIN) {
            int k2 = i / 1536, n = i % 1536;
            float2 v = *(const float2*)(Win + (size_t)n * 384 + 2 * k2);
            g_win_p[i] = pack_bf2(v.x, v.y);
        } else if (i < TIN + TOUT) {
            int j = i - TIN;
            int k2 = j / 384, n = j % 384;
            float2 v = *(const float2*)(Wout + (size_t)n * 768 + 2 * k2);
            g_wout_p[j] = pack_bf2(v.x, v.y);
        } else if (i < TIN + TOUT + TX) {
            int j = i - TIN - TOUT;
            int k2 = j / 64, n = j % 64;
            if (n < 56) {
                float2 vf = *(const float2*)(Wxf + (size_t)n * 768 + 2 * k2);
                float2 vb = *(const float2*)(Wxb + (size_t)n * 768 + 2 * k2);
                g_wx_p[0][j] = pack_bf2(vf.x, vf.y);
                g_wx_p[1][j] = pack_bf2(vb.x, vb.y);
            } else {
                g_wx_p[0][j] = 0u; g_wx_p[1][j] = 0u;
            }
        }
    }
}

// ---------------- mm_in: [xh|z] = xn @ Win  (M=16384,N=1536,K=384), cp.async dbuf ----------------
__global__ __launch_bounds__(256, 2) void mm_in_bf16() {
    const int K = 384, N = 1536, T = 12;
    __shared__ uint32_t As[2][128][20];
    __shared__ uint32_t Bs[2][16][136];
    int tid = threadIdx.x, lane = tid & 31, wid = tid >> 5;
    int wr = (wid & 3) * 32, wc = (wid >> 2) * 64;
    int g = lane >> 2, tg = lane & 3;
    const uint32_t* Ap = (const uint32_t*)g_xnb + (size_t)blockIdx.y * 128 * (K / 2);
    const uint32_t* Bp = g_win_p + blockIdx.x * 128;
    float acc[2][8][4] = {};

    int ar0 = tid >> 2, ar1 = (tid + 256) >> 2, ac = (tid & 3) * 4;
    int bk0 = tid >> 5, bk1 = (tid + 256) >> 5, bn = (tid & 31) * 4;
    uint32_t sA0[2], sA1[2], sB0[2], sB1[2];
#pragma unroll
    for (int s = 0; s < 2; s++) {
        sA0[s] = (uint32_t)__cvta_generic_to_shared(&As[s][ar0][ac]);
        sA1[s] = (uint32_t)__cvta_generic_to_shared(&As[s][ar1][ac]);
        sB0[s] = (uint32_t)__cvta_generic_to_shared(&Bs[s][bk0][bn]);
        sB1[s] = (uint32_t)__cvta_generic_to_shared(&Bs[s][bk1][bn]);
    }
    cpa16(sA0[0], Ap + (size_t)ar0 * (K / 2) + ac);
    cpa16(sA1[0], Ap + (size_t)ar1 * (K / 2) + ac);
    cpa16(sB0[0], Bp + (size_t)bk0 * N + bn);
    cpa16(sB1[0], Bp + (size_t)bk1 * N + bn);
    CPA_COMMIT();

    for (int i = 0; i < T; i++) {
        int s = i & 1;
        if (i + 1 < T) {
            int kh = (i + 1) * 16;
            cpa16(sA0[s ^ 1], Ap + (size_t)ar0 * (K / 2) + kh + ac);
            cpa16(sA1[s ^ 1], Ap + (size_t)ar1 * (K / 2) + kh + ac);
            cpa16(sB0[s ^ 1], Bp + (size_t)(kh + bk0) * N + bn);
            cpa16(sB1[s ^ 1], Bp + (size_t)(kh + bk1) * N + bn);
            CPA_COMMIT();
            CPA_WAIT(1);
        } else {
            CPA_WAIT(0);
        }
        __syncthreads();
#pragma unroll
        for (int ks = 0; ks < 2; ks++) {
            int kb2 = ks * 8;
            uint32_t af[2][4], bf[8][2];
#pragma unroll
            for (int mi = 0; mi < 2; mi++) {
                int r0 = wr + mi * 16;
                af[mi][0] = As[s][r0 + g][kb2 + tg];
                af[mi][1] = As[s][r0 + g + 8][kb2 + tg];
                af[mi][2] = As[s][r0 + g][kb2 + tg + 4];
                af[mi][3] = As[s][r0 + g + 8][kb2 + tg + 4];
            }
#pragma unroll
            for (int ni = 0; ni < 8; ni++) {
                bf[ni][0] = Bs[s][kb2 + tg][wc + ni * 8 + g];
                bf[ni][1] = Bs[s][kb2 + tg + 4][wc + ni * 8 + g];
            }
#pragma unroll
            for (int mi = 0; mi < 2; mi++)
#pragma unroll
                for (int ni = 0; ni < 8; ni++) mma_bf16(acc[mi][ni], af[mi], bf[ni]);
        }
        __syncthreads();
    }
    size_t rbase = (size_t)blockIdx.y * 128;
    if (blockIdx.x < 6) {
        uint32_t* C = (uint32_t*)g_xh;
        int cb = blockIdx.x * 128;
#pragma unroll
        for (int mi = 0; mi < 2; mi++)
#pragma unroll
            for (int ni = 0; ni < 8; ni++) {
                int r = wr + mi * 16 + g, c = cb + wc + ni * 8 + tg * 2;
                C[((rbase + r) * DI + c) >> 1]     = pack_bf2(acc[mi][ni][0], acc[mi][ni][1]);
                C[((rbase + r + 8) * DI + c) >> 1] = pack_bf2(acc[mi][ni][2], acc[mi][ni][3]);
            }
    } else {
        int cb = (blockIdx.x - 6) * 128;
#pragma unroll
        for (int mi = 0; mi < 2; mi++)
#pragma unroll
            for (int ni = 0; ni < 8; ni++) {
                int r = wr + mi * 16 + g, c = cb + wc + ni * 8 + tg * 2;
                *(float2*)(g_z + (rbase + r) * DI + c)     = make_float2(acc[mi][ni][0], acc[mi][ni][1]);
                *(float2*)(g_z + (rbase + r + 8) * DI + c) = make_float2(acc[mi][ni][2], acc[mi][ni][3]);
            }
    }
}

// ---------------- mm_out: out = x + (yf+yr) @ Wout (M=16384,N=384,K=768), dbuf 1-sync ----------------
__global__ __launch_bounds__(256, 2) void mm_out_bf16(const float* __restrict__ xres,
                                                      float* __restrict__ out) {
    const int K = 768, N = 384, T = 24;
    __shared__ uint32_t As[2][128][20];
    __shared__ uint32_t Bs[2][16][136];
    int tid = threadIdx.x, lane = tid & 31, wid = tid >> 5;
    int wr = (wid & 3) * 32, wc = (wid >> 2) * 64;
    int g = lane >> 2, tg = lane & 3;
    const uint32_t* A0 = (const uint32_t*)g_y[0] + (size_t)blockIdx.y * 128 * (K / 2);
    const uint32_t* A1 = (const uint32_t*)g_y[1] + (size_t)blockIdx.y * 128 * (K / 2);
    const uint32_t* Bp = g_wout_p + blockIdx.x * 128;
    float acc[2][8][4] = {};

    int ar0 = tid >> 2, ar1 = (tid + 256) >> 2, ac = (tid & 3) * 4;
    int bk0 = tid >> 5, bk1 = (tid + 256) >> 5, bn = (tid & 31) * 4;
    uint4 ra0, ra1, sa0, sa1, rb0, rb1;
    ra0 = *(const uint4*)(A0 + (size_t)ar0 * (K / 2) + ac);
    sa0 = *(const uint4*)(A1 + (size_t)ar0 * (K / 2) + ac);
    ra1 = *(const uint4*)(A0 + (size_t)ar1 * (K / 2) + ac);
    sa1 = *(const uint4*)(A1 + (size_t)ar1 * (K / 2) + ac);
    rb0 = *(const uint4*)(Bp + (size_t)bk0 * N + bn);
    rb1 = *(const uint4*)(Bp + (size_t)bk1 * N + bn);

    for (int i = 0; i < T; i++) {
        int s = i & 1;
        As[s][ar0][ac + 0] = hadd2_bf2(ra0.x, sa0.x);
        As[s][ar0][ac + 1] = hadd2_bf2(ra0.y, sa0.y);
        As[s][ar0][ac + 2] = hadd2_bf2(ra0.z, sa0.z);
        As[s][ar0][ac + 3] = hadd2_bf2(ra0.w, sa0.w);
        As[s][ar1][ac + 0] = hadd2_bf2(ra1.x, sa1.x);
        As[s][ar1][ac + 1] = hadd2_bf2(ra1.y, sa1.y);
        As[s][ar1][ac + 2] = hadd2_bf2(ra1.z, sa1.z);
        As[s][ar1][ac + 3] = hadd2_bf2(ra1.w, sa1.w);
        *(uint4*)&Bs[s][bk0][bn] = rb0;
        *(uint4*)&Bs[s][bk1][bn] = rb1;
        __syncthreads();
        if (i + 1 < T) {
            int kh = (i + 1) * 16;
            ra0 = *(const uint4*)(A0 + (size_t)ar0 * (K / 2) + kh + ac);
            sa0 = *(const uint4*)(A1 + (size_t)ar0 * (K / 2) + kh + ac);
            ra1 = *(const uint4*)(A0 + (size_t)ar1 * (K / 2) + kh + ac);
            sa1 = *(const uint4*)(A1 + (size_t)ar1 * (K / 2) + kh + ac);
            rb0 = *(const uint4*)(Bp + (size_t)(kh + bk0) * N + bn);
            rb1 = *(const uint4*)(Bp + (size_t)(kh + bk1) * N + bn);
        }
#pragma unroll
        for (int ks = 0; ks < 2; ks++) {
            int kb2 = ks * 8;
            uint32_t af[2][4], bf[8][2];
#pragma unroll
            for (int mi = 0; mi < 2; mi++) {
                int r0 = wr + mi * 16;
                af[mi][0] = As[s][r0 + g][kb2 + tg];
                af[mi][1] = As[s][r0 + g + 8][kb2 + tg];
                af[mi][2] = As[s][r0 + g][kb2 + tg + 4];
                af[mi][3] = As[s][r0 + g + 8][kb2 + tg + 4];
            }
#pragma unroll
            for (int ni = 0; ni < 8; ni++) {
                bf[ni][0] = Bs[s][kb2 + tg][wc + ni * 8 + g];
                bf[ni][1] = Bs[s][kb2 + tg + 4][wc + ni * 8 + g];
            }
#pragma unroll
            for (int mi = 0; mi < 2; mi++)
#pragma unroll
                for (int ni = 0; ni < 8; ni++) mma_bf16(acc[mi][ni], af[mi], bf[ni]);
        }
        __syncthreads();
    }
    size_t rbase = (size_t)blockIdx.y * 128;
    int cbase = blockIdx.x * 128;
#pragma unroll
    for (int mi = 0; mi < 2; mi++)
#pragma unroll
        for (int ni = 0; ni < 8; ni++) {
            int r = wr + mi * 16 + g, c = wc + ni * 8 + tg * 2;
            size_t o0 = (rbase + r) * N + cbase + c;
            size_t o1 = (rbase + r + 8) * N + cbase + c;
            out[o0]     = acc[mi][ni][0] + xres[o0];
            out[o0 + 1] = acc[mi][ni][1] + xres[o0 + 1];
            out[o1]     = acc[mi][ni][2] + xres[o1];
            out[o1 + 1] = acc[mi][ni][3] + xres[o1 + 1];
        }
}

// ---------------- mm_x: dbc = xc @ Wx (M=16384,N=64->56,K=768), cp.async dbuf ----------------
__global__ __launch_bounds__(256, 2) void mm_x_bf16() {
    const int K = 768, T = 24;
    int dir = blockIdx.z;
    __shared__ uint32_t As[2][128][20];
    __shared__ uint32_t Bs[2][16][72];
    int tid = threadIdx.x, lane = tid & 31, wid = tid >> 5;
    int wr = wid * 16;
    int g = lane >> 2, tg = lane & 3;
    const uint32_t* Ap = (const uint32_t*)g_xc[dir] + (size_t)blockIdx.y * 128 * (K / 2);
    const uint32_t* Bp = g_wx_p[dir];
    float acc[8][4] = {};

    int ar0 = tid >> 2, ar1 = (tid + 256) >> 2, ac = (tid & 3) * 4;
    int bk = tid >> 4, bn = (tid & 15) * 4;
    uint32_t sA0[2], sA1[2], sB[2];
#pragma unroll
    for (int s = 0; s < 2; s++) {
        sA0[s] = (uint32_t)__cvta_generic_to_shared(&As[s][ar0][ac]);
        sA1[s] = (uint32_t)__cvta_generic_to_shared(&As[s][ar1][ac]);
        sB[s]  = (uint32_t)__cvta_generic_to_shared(&Bs[s][bk][bn]);
    }
    cpa16(sA0[0], Ap + (size_t)ar0 * (K / 2) + ac);
    cpa16(sA1[0], Ap + (size_t)ar1 * (K / 2) + ac);
    cpa16(sB[0],  Bp + (size_t)bk * 64 + bn);
    CPA_COMMIT();

    for (int i = 0; i < T; i++) {
        int s = i & 1;
        if (i + 1 < T) {
            int kh = (i + 1) * 16;
            cpa16(sA0[s ^ 1], Ap + (size_t)ar0 * (K / 2) + kh + ac);
            cpa16(sA1[s ^ 1], Ap + (size_t)ar1 * (K / 2) + kh + ac);
            cpa16(sB[s ^ 1],  Bp + (size_t)(kh + bk) * 64 + bn);
            CPA_COMMIT();
            CPA_WAIT(1);
        } else {
            CPA_WAIT(0);
        }
        __syncthreads();
#pragma unroll
        for (int ks = 0; ks < 2; ks++) {
            int kb2 = ks * 8;
            uint32_t af[4], bf[8][2];
            af[0] = As[s][wr + g][kb2 + tg];
            af[1] = As[s][wr + g + 8][kb2 + tg];
            af[2] = As[s][wr + g][kb2 + tg + 4];
            af[3] = As[s][wr + g + 8][kb2 + tg + 4];
#pragma unroll
            for (int ni = 0; ni < 8; ni++) {
                bf[ni][0] = Bs[s][kb2 + tg][ni * 8 + g];
                bf[ni][1] = Bs[s][kb2 + tg + 4][ni * 8 + g];
            }
#pragma unroll
            for (int ni = 0; ni < 8; ni++) mma_bf16(acc[ni], af, bf[ni]);
        }
        __syncthreads();
    }
    size_t rbase = (size_t)blockIdx.y * 128;
#pragma unroll
    for (int ni = 0; ni < 8; ni++) {
        int c = ni * 8 + tg * 2;
        if (c < 56) {
            int r = wr + g;
            float* o0 = g_dbc[dir] + (rbase + r) * DBCW + c;
            float* o1 = g_dbc[dir] + (rbase + r + 8) * DBCW + c;
            o0[0] = acc[ni][0]; o0[1] = acc[ni][1];
            o1[0] = acc[ni][2]; o1[1] = acc[ni][3];
        }
    }
}

// ---------------- causal conv: 16 chunks, 2-block channel split, packed ----------------
__global__ __launch_bounds__(192) void conv_chunk_kernel(const float* __restrict__ cw_f,
                                                         const float* __restrict__ cb_f,
                                                         const float* __restrict__ cw_b,
                                                         const float* __restrict__ cb_b) {
    int dir = blockIdx.z;
    int bb = blockIdx.y >> 4, ch = blockIdx.y & 15;
    int d2 = blockIdx.x * 192 + threadIdx.x;
    int d = d2 * 2;
    int l0 = ch * CHTC;
    const float* cw = dir ? cw_b : cw_f;
    float4 wa = *(const float4*)(cw + d * 4);
    float4 wb = *(const float4*)(cw + d * 4 + 4);
    float2 bias = *(const float2*)((dir ? cb_b : cb_f) + d);
    const uint32_t* xp = (const uint32_t*)g_xh + (size_t)bb * Ll * (DI / 2) + d2;
    uint32_t* yo = (uint32_t*)g_xc[dir] + ((size_t)bb * Ll + l0) * (DI / 2) + d2;
    float a1 = 0.f, a2 = 0.f, a3 = 0.f;
    float b1 = 0.f, b2 = 0.f, b3 = 0.f;
    {
        int lk;
        lk = l0 - 1; if (lk >= 0) { float2 v = unpk_bf2(xp[(size_t)(dir ? (Ll - 1 - lk) : lk) * (DI / 2)]); a1 = v.x; b1 = v.y; }
        lk = l0 - 2; if (lk >= 0) { float2 v = unpk_bf2(xp[(size_t)(dir ? (Ll - 1 - lk) : lk) * (DI / 2)]); a2 = v.x; b2 = v.y; }
        lk = l0 - 3; if (lk >= 0) { float2 v = unpk_bf2(xp[(size_t)(dir ? (Ll - 1 - lk) : lk) * (DI / 2)]); a3 = v.x; b3 = v.y; }
    }
    const uint32_t* xq = xp + (size_t)(dir ? (Ll - 1 - l0) : l0) * (DI / 2);
    intptr_t step = (dir ? -(intptr_t)(DI / 2) : (intptr_t)(DI / 2));
    for (int l = 0; l < CHTC; l += 4) {
        float2 xv[4];
#pragma unroll
        for (int j = 0; j < 4; j++) { xv[j] = unpk_bf2(*xq); xq += step; }
#pragma unroll
        for (int j = 0; j < 4; j++) {
            float sa = bias.x + wa.w * xv[j].x + wa.z * a1 + wa.y * a2 + wa.x * a3;
            float sb = bias.y + wb.w * xv[j].y + wb.z * b1 + wb.y * b2 + wb.x * b3;
            a3 = a2; a2 = a1; a1 = xv[j].x;
            b3 = b2; b2 = b1; b1 = xv[j].y;
            sa = sa * (1.f / (1.f + __expf(-sa)));
            sb = sb * (1.f / (1.f + __expf(-sb)));
            yo[(size_t)(l + j) * (DI / 2)] = pack_bf2(sa, sb);
        }
    }
}

// ---------------- dt_proj + softplus (float4 smem, fast log) ----------------
__global__ __launch_bounds__(256) void dtproj_kernel(const float* __restrict__ dtw_f,
                                                     const float* __restrict__ dtb_f,
                                                     const float* __restrict__ dtw_b,
                                                     const float* __restrict__ dtb_b) {
    int dir = blockIdx.z;
    int col = blockIdx.x * 256 + threadIdx.x;
    int r0 = blockIdx.y * 32;
    const float* Wd = dir ? dtw_b : dtw_f;
    float4 w[6];
#pragma unroll
    for (int j = 0; j < 6; j++) w[j] = *(const float4*)(Wd + col * DTR + j * 4);
    float bias = (dir ? dtb_b : dtb_f)[col];
    __shared__ __align__(16) float sdt[32 * DTR];
    if (threadIdx.x < 192) {
        int rr = threadIdx.x / 6, j = threadIdx.x % 6;
        *(float4*)&sdt[rr * DTR + j * 4] =
            *(const float4*)(g_dbc[dir] + (size_t)(r0 + rr) * DBCW + j * 4);
    }
    __syncthreads();
    for (int rr = 0; rr < 32; rr++) {
        float acc = bias;
#pragma unroll
        for (int j = 0; j < 6; j++) {
            float4 v = *(const float4*)&sdt[rr * DTR + j * 4];
            acc += v.x * w[j].x + v.y * w[j].y + v.z * w[j].z + v.w * w[j].w;
        }
        float sp = (acc > 20.f) ? acc : __logf(1.f + __expf(acc));
        g_delta[dir][(size_t)(r0 + rr) * DI + col] = __float2bfloat16(sp);
    }
}

// ---------------- scan pass 1: chunks 0..6 only (chunk 7 state unused) ----------------
__global__ __launch_bounds__(64) void scan_pass1(const float* __restrict__ Alog_f,
                                                 const float* __restrict__ Alog_b) {
    int dir = blockIdx.z;
    int bb = blockIdx.y / 7, ch = blockIdx.y % 7;
    int d = blockIdx.x * 64 + threadIdx.x;
    int tb = ch * CHT;
    const float* Alog = dir ? Alog_b : Alog_f;
    const __nv_bfloat16* delta = g_delta[dir] + ((size_t)bb * Ll + tb) * DI + d;
    const __nv_bfloat16* u     = g_xc[dir]   + ((size_t)bb * Ll + tb) * DI + d;
    const float* dbc           = g_dbc[dir]  + ((size_t)bb * Ll + tb) * DBCW;

    float A[NS];
#pragma unroll
    for (int n = 0; n < NS; n++) A[n] = -__expf(Alog[d * NS + n]);
    bool fast = true;
#pragma unroll
    for (int n = 1; n < NS; n++)
        fast = fast && (fabsf(A[n] - (float)(n + 1) * A[0]) <= 1e-5f * fabsf(A[n]));

    __shared__ float4 sB4[8][4];
    float h[NS];
#pragma unroll
    for (int n = 0; n < NS; n++) h[n] = 0.f;
    float sdt = 0.f;

    for (int t0 = 0; t0 < CHT; t0 += 8) {
        float dl[8], ul[8], ql[8];
#pragma unroll
        for (int i = 0; i < 8; i++) {
            dl[i] = __bfloat162float(delta[(size_t)(t0 + i) * DI]);
            ul[i] = __bfloat162float(u[(size_t)(t0 + i) * DI]);
            ql[i] = __expf(dl[i] * A[0]);
        }
        __syncthreads();
        if (threadIdx.x < 32) {
            int tt = threadIdx.x >> 2, j = threadIdx.x & 3;
            sB4[tt][j] = *(const float4*)(dbc + (size_t)(t0 + tt) * DBCW + DTR + j * 4);
        }
        __syncthreads();
#pragma unroll
        for (int i = 0; i < 8; i++) {
            float4 b0 = sB4[i][0], b1 = sB4[i][1], b2 = sB4[i][2], b3 = sB4[i][3];
            float Bv[NS] = {b0.x, b0.y, b0.z, b0.w, b1.x, b1.y, b1.z, b1.w,
                            b2.x, b2.y, b2.z, b2.w, b3.x, b3.y, b3.z, b3.w};
            float dt = dl[i];
            float du = dt * ul[i];
            sdt += dt;
            if (fast) {
                float q = ql[i];
                float q2 = q * q, q4 = q2 * q2, q8 = q4 * q4;
                float q3 = q2 * q, q5 = q4 * q, q6 = q4 * q2, q7 = q4 * q3;
                float pw[NS] = {q, q2, q3, q4, q5, q6, q7, q8,
                                q8 * q, q8 * q2, q8 * q3, q8 * q4,
                                q8 * q5, q8 * q6, q8 * q7, q8 * q8};
#pragma unroll
                for (int n = 0; n < NS; n++) h[n] = h[n] * pw[n] + du * Bv[n];
            } else {
#pragma unroll
                for (int n = 0; n < NS; n++) {
                    float dA = __expf(dt * A[n]);
                    h[n] = h[n] * dA + du * Bv[n];
                }
            }
        }
    }
#pragma unroll
    for (int n = 0; n < NS; n++) g_hc[dir][bb][ch][n][d] = h[n];
    g_dts[dir][bb][ch][d] = sdt;
}

// ---------------- scan pass 3: combine entry inline, then full scan ----------------
__global__ __launch_bounds__(64) void scan_pass3(const float* __restrict__ Alog_f,
                                                 const float* __restrict__ Alog_b,
                                                 const float* __restrict__ Dv_f,
                                                 const float* __restrict__ Dv_b) {
    int dir = blockIdx.z;
    int bb = blockIdx.y >> 3, ch = blockIdx.y & 7;
    int d = blockIdx.x * 64 + threadIdx.x;
    int tb = ch * CHT;
    const float* Alog = dir ? Alog_b : Alog_f;
    const float* Dvp  = dir ? Dv_b  : Dv_f;
    const __nv_bfloat16* delta = g_delta[dir] + ((size_t)bb * Ll + tb) * DI + d;
    const __nv_bfloat16* u     = g_xc[dir]   + ((size_t)bb * Ll + tb) * DI + d;
    const float* dbc           = g_dbc[dir]  + ((size_t)bb * Ll + tb) * DBCW;
    const float* zb            = g_z + (size_t)bb * Ll * DI + d;
    __nv_bfloat16* yout        = g_y[dir] + (size_t)bb * Ll * DI + d;

    float A[NS];
#pragma unroll
    for (int n = 0; n < NS; n++) A[n] = -__expf(Alog[d * NS + n]);
    bool fast = true;
#pragma unroll
    for (int n = 1; n < NS; n++)
        fast = fast && (fabsf(A[n] - (float)(n + 1) * A[0]) <= 1e-5f * fabsf(A[n]));
    float Dv = Dvp[d];

    // entry state: sequentially combine chunks 0..ch-1
    float h[NS];
#pragma unroll
    for (int n = 0; n < NS; n++) h[n] = 0.f;
    for (int j = 0; j < ch; j++) {
        float S = g_dts[dir][bb][j][d];
        if (fast) {
            float r = __expf(A[0] * S);
            float r2 = r * r, r4 = r2 * r2, r8 = r4 * r4;
            float r3 = r2 * r, r5 = r4 * r, r6 = r4 * r2, r7 = r4 * r3;
            float pw[NS] = {r, r2, r3, r4, r5, r6, r7, r8,
                            r8 * r, r8 * r2, r8 * r3, r8 * r4,
                            r8 * r5, r8 * r6, r8 * r7, r8 * r8};
#pragma unroll
            for (int n = 0; n < NS; n++) h[n] = g_hc[dir][bb][j][n][d] + pw[n] * h[n];
        } else {
#pragma unroll
            for (int n = 0; n < NS; n++)
                h[n] = g_hc[dir][bb][j][n][d] + __expf(A[n] * S) * h[n];
        }
    }

    __shared__ float4 sBC[8][8];
    for (int t0 = 0; t0 < CHT; t0 += 8) {
        float dl[8], ul[8], zl[8], ql[8];
#pragma unroll
        for (int i = 0; i < 8; i++) {
            dl[i] = __bfloat162float(delta[(size_t)(t0 + i) * DI]);
            ul[i] = __bfloat162float(u[(size_t)(t0 + i) * DI]);
            int t = tb + t0 + i;
            int op = dir ? (Ll - 1 - t) : t;
            zl[i] = zb[(size_t)op * DI];
            ql[i] = __expf(dl[i] * A[0]);
        }
        __syncthreads();
        {
            int tt = threadIdx.x >> 3, j = threadIdx.x & 7;
            sBC[tt][j] = *(const float4*)(dbc + (size_t)(t0 + tt) * DBCW + DTR + j * 4);
        }
        __syncthreads();
#pragma unroll
        for (int i = 0; i < 8; i++) {
            float4 b0 = sBC[i][0], b1 = sBC[i][1], b2 = sBC[i][2], b3 = sBC[i][3];
            float4 c0 = sBC[i][4], c1 = sBC[i][5], c2 = sBC[i][6], c3 = sBC[i][7];
            float Bv[NS] = {b0.x, b0.y, b0.z, b0.w, b1.x, b1.y, b1.z, b1.w,
                            b2.x, b2.y, b2.z, b2.w, b3.x, b3.y, b3.z, b3.w};
            float Cv[NS] = {c0.x, c0.y, c0.z, c0.w, c1.x, c1.y, c1.z, c1.w,
                            c2.x, c2.y, c2.z, c2.w, c3.x, c3.y, c3.z, c3.w};
            float dt = dl[i];
            float du = dt * ul[i];
            float y = 0.f;
            if (fast) {
                float q = ql[i];
                float q2 = q * q, q4 = q2 * q2, q8 = q4 * q4;
                float q3 = q2 * q, q5 = q4 * q, q6 = q4 * q2, q7 = q4 * q3;
                float pw[NS] = {q, q2, q3, q4, q5, q6, q7, q8,
                                q8 * q, q8 * q2, q8 * q3, q8 * q4,
                                q8 * q5, q8 * q6, q8 * q7, q8 * q8};
#pragma unroll
                for (int n = 0; n < NS; n++) {
                    h[n] = h[n] * pw[n] + du * Bv[n];
                    y += h[n] * Cv[n];
                }
            } else {
#pragma unroll
                for (int n = 0; n < NS; n++) {
                    float dA = __expf(dt * A[n]);
                    h[n] = h[n] * dA + du * Bv[n];
                    y += h[n] * Cv[n];
                }
            }
            y += ul[i] * Dv;
            float z = zl[i];
            float sz = z * (1.f / (1.f + __expf(-z)));
            int t = tb + t0 + i;
            int op = dir ? (Ll - 1 - t) : t;
            yout[(size_t)op * DI] = __float2bfloat16(y * sz);
        }
    }
}

// ---------------- launch ----------------
extern "C" void kernel_launch(void* const* d_in, const int* in_sizes, int n_in,
                              void* d_out, int out_size) {
    const float* x        = (const float*)d_in[0];
    const float* ln_w     = (const float*)d_in[1];
    const float* ln_b     = (const float*)d_in[2];
    const float* in_proj  = (const float*)d_in[3];
    const float* out_proj = (const float*)d_in[4];
    const float* cw_f     = (const float*)d_in[5];
    const float* cb_f     = (const float*)d_in[6];
    const float* xw_f     = (const float*)d_in[7];
    const float* dtw_f    = (const float*)d_in[8];
    const float* dtb_f    = (const float*)d_in[9];
    const float* Alog_f   = (const float*)d_in[10];
    const float* Dv_f     = (const float*)d_in[11];
    const float* cw_b     = (const float*)d_in[12];
    const float* cb_b     = (const float*)d_in[13];
    const float* xw_b     = (const float*)d_in[14];
    const float* dtw_b    = (const float*)d_in[15];
    const float* dtb_b    = (const float*)d_in[16];
    const float* Alog_b   = (const float*)d_in[17];
    const float* Dv_b     = (const float*)d_in[18];
    float* out = (float*)d_out;

    int prep_blocks = LNBLK + (TIN + TOUT + TX + 255) / 256;
    prep_kernel<<<prep_blocks, 256>>>(x, ln_w, ln_b, in_proj, out_proj, xw_f, xw_b);
    mm_in_bf16<<<dim3(12, 128), 256>>>();
    conv_chunk_kernel<<<dim3(2, Bb * NCHC, 2), 192>>>(cw_f, cb_f, cw_b, cb_b);
    mm_x_bf16<<<dim3(1, 128, 2), 256>>>();
    dtproj_kernel<<<dim3(3, BLr / 32, 2), 256>>>(dtw_f, dtb_f, dtw_b, dtb_b);
    scan_pass1<<<dim3(12, Bb * 7, 2), 64>>>(Alog_f, Alog_b);
    scan_pass3<<<dim3(12, 128, 2), 64>>>(Alog_f, Alog_b, Dv_f, Dv_b);
    mm_out_bf16<<<dim3(3, 128), 256>>>(x, out);
}